// round 1
// baseline (speedup 1.0000x reference)
#include <cuda_runtime.h>
#include <math.h>

// Problem constants
#define BATCH 8192
#define DIM   1024   // D
#define HID   512    // H
#define EDIM  256    // E
#define NEXP  16     // 12 task-specific (t*4+s) + 4 shared
#define TTASK 3

// -------- device scratch (no allocations allowed) --------
__device__ float g_h   [(size_t)NEXP * BATCH * HID];   // layer-1 activations, per expert [B,H]
__device__ float g_eo  [(size_t)NEXP * BATCH * EDIM];  // expert outputs, per expert [B,E]
__device__ float g_gate[(size_t)TTASK * BATCH * 8];    // task gates [t][b][8]
__device__ float g_gsh [(size_t)BATCH * 16];           // shared gate [b][16]

// ============================================================================
// Tiled SGEMM + bias + ReLU:  Y[M,N] = relu(A[M,K] @ W[K,N] + bias[N])
// BM=128, BN=128, BK (template), 256 threads, 8x8 per thread, double-buffered.
// M=8192, N in {512,256}, K in {1024,512} -> all tiles exact, no bounds checks.
// ============================================================================
template<int BK, int N, int K>
__device__ __forceinline__ void sgemm_bias_relu(
    const float* __restrict__ A, const float* __restrict__ W,
    const float* __restrict__ bias, float* __restrict__ Y)
{
    constexpr int BM = 128, BN = 128, TM = 8, TN = 8;
    __shared__ float As[2][BK][BM];   // transposed A tile: [k][m]
    __shared__ float Bs[2][BK][BN];   // [k][n]

    const int tid = threadIdx.x;
    const int bm = blockIdx.y * BM;
    const int bn = blockIdx.x * BN;

    // A-tile loader mapping: 128x8 floats, one float4 per thread
    const int a_row = tid >> 1;           // 0..127
    const int a_col = (tid & 1) << 2;     // 0 or 4
    // B-tile loader mapping: 8x128 floats, one float4 per thread
    const int b_row = tid >> 5;           // 0..7
    const int b_col = (tid & 31) << 2;    // 0..124

    const float* Ag = A + (size_t)(bm + a_row) * K + a_col;
    const float* Wg = W + (size_t)b_row * N + bn + b_col;

    float acc[TM][TN];
    #pragma unroll
    for (int i = 0; i < TM; i++)
        #pragma unroll
        for (int j = 0; j < TN; j++) acc[i][j] = 0.0f;

    // prologue: tile k0 = 0 into buffer 0
    {
        float4 a4 = *(const float4*)Ag;
        float4 b4 = *(const float4*)Wg;
        As[0][a_col + 0][a_row] = a4.x;
        As[0][a_col + 1][a_row] = a4.y;
        As[0][a_col + 2][a_row] = a4.z;
        As[0][a_col + 3][a_row] = a4.w;
        *(float4*)&Bs[0][b_row][b_col] = b4;
    }
    __syncthreads();

    const int tx = tid & 15;   // n-tile position
    const int ty = tid >> 4;   // m-tile position
    int buf = 0;

    for (int k0 = 0; k0 < K; k0 += BK) {
        float4 a4n, b4n;
        const bool notlast = (k0 + BK < K);
        if (notlast) {
            a4n = *(const float4*)(Ag + (k0 + BK));
            b4n = *(const float4*)(Wg + (size_t)(k0 + BK) * N);
        }
        #pragma unroll
        for (int kk = 0; kk < BK; kk++) {
            float ar[TM], br[TN];
            *(float4*)&ar[0] = *(const float4*)&As[buf][kk][ty * TM];
            *(float4*)&ar[4] = *(const float4*)&As[buf][kk][ty * TM + 4];
            *(float4*)&br[0] = *(const float4*)&Bs[buf][kk][tx * TN];
            *(float4*)&br[4] = *(const float4*)&Bs[buf][kk][tx * TN + 4];
            #pragma unroll
            for (int i = 0; i < TM; i++)
                #pragma unroll
                for (int j = 0; j < TN; j++)
                    acc[i][j] += ar[i] * br[j];
        }
        if (notlast) {
            buf ^= 1;
            As[buf][a_col + 0][a_row] = a4n.x;
            As[buf][a_col + 1][a_row] = a4n.y;
            As[buf][a_col + 2][a_row] = a4n.z;
            As[buf][a_col + 3][a_row] = a4n.w;
            *(float4*)&Bs[buf][b_row][b_col] = b4n;
            __syncthreads();
        }
    }

    // epilogue: bias + relu, vectorized stores
    float bv[TN];
    *(float4*)&bv[0] = *(const float4*)(bias + bn + tx * TN);
    *(float4*)&bv[4] = *(const float4*)(bias + bn + tx * TN + 4);
    #pragma unroll
    for (int i = 0; i < TM; i++) {
        float4 o0, o1;
        o0.x = fmaxf(acc[i][0] + bv[0], 0.0f);
        o0.y = fmaxf(acc[i][1] + bv[1], 0.0f);
        o0.z = fmaxf(acc[i][2] + bv[2], 0.0f);
        o0.w = fmaxf(acc[i][3] + bv[3], 0.0f);
        o1.x = fmaxf(acc[i][4] + bv[4], 0.0f);
        o1.y = fmaxf(acc[i][5] + bv[5], 0.0f);
        o1.z = fmaxf(acc[i][6] + bv[6], 0.0f);
        o1.w = fmaxf(acc[i][7] + bv[7], 0.0f);
        size_t row = (size_t)(bm + ty * TM + i) * N + bn + tx * TN;
        *(float4*)(Y + row)     = o0;
        *(float4*)(Y + row + 4) = o1;
    }
}

// ---------------- layer 1: 16 x [8192,1024]@[1024,512] ----------------
__global__ __launch_bounds__(256) void l1_kernel(
    const float* __restrict__ x_tasks, const float* __restrict__ x_shared,
    const float* __restrict__ W_spec1, const float* __restrict__ b_spec1,
    const float* __restrict__ W_sh1,   const float* __restrict__ b_sh1)
{
    const int e = blockIdx.z;
    const float *A, *W, *bias;
    if (e < 12) {
        A    = x_tasks + (size_t)(e >> 2) * BATCH * DIM;
        W    = W_spec1 + (size_t)e * DIM * HID;
        bias = b_spec1 + (size_t)e * HID;
    } else {
        A    = x_shared;
        W    = W_sh1 + (size_t)(e - 12) * DIM * HID;
        bias = b_sh1 + (size_t)(e - 12) * HID;
    }
    sgemm_bias_relu<8, HID, DIM>(A, W, bias, g_h + (size_t)e * BATCH * HID);
}

// ---------------- layer 2: 16 x [8192,512]@[512,256] ----------------
__global__ __launch_bounds__(256) void l2_kernel(
    const float* __restrict__ W_spec2, const float* __restrict__ b_spec2,
    const float* __restrict__ W_sh2,   const float* __restrict__ b_sh2)
{
    const int e = blockIdx.z;
    const float *W, *bias;
    if (e < 12) {
        W    = W_spec2 + (size_t)e * HID * EDIM;
        bias = b_spec2 + (size_t)e * EDIM;
    } else {
        W    = W_sh2 + (size_t)(e - 12) * HID * EDIM;
        bias = b_sh2 + (size_t)(e - 12) * EDIM;
    }
    sgemm_bias_relu<8, EDIM, HID>(g_h + (size_t)e * BATCH * HID, W, bias,
                                  g_eo + (size_t)e * BATCH * EDIM);
}

// ---------------- gates: one warp per row; rows 0..3*B-1 task, 3*B..4*B-1 shared ----
__global__ __launch_bounds__(256) void gates_kernel(
    const float* __restrict__ x_tasks, const float* __restrict__ x_shared,
    const float* __restrict__ W_gate,  const float* __restrict__ b_gate,
    const float* __restrict__ W_gsh,   const float* __restrict__ b_gsh)
{
    const int warp = (blockIdx.x * blockDim.x + threadIdx.x) >> 5;
    const int lane = threadIdx.x & 31;
    const int t = warp >> 13;          // warp / 8192
    const int b = warp & (BATCH - 1);

    if (t < TTASK) {
        const float* x = x_tasks + ((size_t)t * BATCH + b) * DIM;
        const float* W = W_gate + (size_t)t * DIM * 8;
        float s[8] = {0,0,0,0,0,0,0,0};
        for (int d = lane; d < DIM; d += 32) {
            float xv = x[d];
            float4 w0 = *(const float4*)(W + (size_t)d * 8);
            float4 w1 = *(const float4*)(W + (size_t)d * 8 + 4);
            s[0] += xv * w0.x; s[1] += xv * w0.y; s[2] += xv * w0.z; s[3] += xv * w0.w;
            s[4] += xv * w1.x; s[5] += xv * w1.y; s[6] += xv * w1.z; s[7] += xv * w1.w;
        }
        #pragma unroll
        for (int o = 0; o < 8; o++)
            #pragma unroll
            for (int off = 16; off > 0; off >>= 1)
                s[o] += __shfl_xor_sync(0xffffffffu, s[o], off);
        if (lane == 0) {
            float mx = -1e30f;
            #pragma unroll
            for (int o = 0; o < 8; o++) { s[o] += b_gate[t * 8 + o]; mx = fmaxf(mx, s[o]); }
            float sum = 0.0f;
            #pragma unroll
            for (int o = 0; o < 8; o++) { s[o] = expf(s[o] - mx); sum += s[o]; }
            float inv = 1.0f / sum;
            #pragma unroll
            for (int o = 0; o < 8; o++)
                g_gate[((size_t)t * BATCH + b) * 8 + o] = s[o] * inv;
        }
    } else {
        const float* x = x_shared + (size_t)b * DIM;
        float s[16];
        #pragma unroll
        for (int o = 0; o < 16; o++) s[o] = 0.0f;
        for (int d = lane; d < DIM; d += 32) {
            float xv = x[d];
            float4 w0 = *(const float4*)(W_gsh + (size_t)d * 16);
            float4 w1 = *(const float4*)(W_gsh + (size_t)d * 16 + 4);
            float4 w2 = *(const float4*)(W_gsh + (size_t)d * 16 + 8);
            float4 w3 = *(const float4*)(W_gsh + (size_t)d * 16 + 12);
            s[ 0] += xv * w0.x; s[ 1] += xv * w0.y; s[ 2] += xv * w0.z; s[ 3] += xv * w0.w;
            s[ 4] += xv * w1.x; s[ 5] += xv * w1.y; s[ 6] += xv * w1.z; s[ 7] += xv * w1.w;
            s[ 8] += xv * w2.x; s[ 9] += xv * w2.y; s[10] += xv * w2.z; s[11] += xv * w2.w;
            s[12] += xv * w3.x; s[13] += xv * w3.y; s[14] += xv * w3.z; s[15] += xv * w3.w;
        }
        #pragma unroll
        for (int o = 0; o < 16; o++)
            #pragma unroll
            for (int off = 16; off > 0; off >>= 1)
                s[o] += __shfl_xor_sync(0xffffffffu, s[o], off);
        if (lane == 0) {
            float mx = -1e30f;
            #pragma unroll
            for (int o = 0; o < 16; o++) { s[o] += b_gsh[o]; mx = fmaxf(mx, s[o]); }
            float sum = 0.0f;
            #pragma unroll
            for (int o = 0; o < 16; o++) { s[o] = expf(s[o] - mx); sum += s[o]; }
            float inv = 1.0f / sum;
            #pragma unroll
            for (int o = 0; o < 16; o++)
                g_gsh[(size_t)b * 16 + o] = s[o] * inv;
        }
    }
}

// ---------------- combine: one block per batch row, thread e = output column ----
// out[t][b][e] (t<3)  = sum_s gate[t][b][s]*eo[t*4+s][b][e] + sum_s gate[t][b][4+s]*eo[12+s][b][e]
// out[3][b][e]        = sum_{j<12} gsh[b][j]*eo[j][b][e] + sum_s gsh[b][12+s]*eo[12+s][b][e]
__global__ __launch_bounds__(256) void combine_kernel(float* __restrict__ out)
{
    const int b = blockIdx.x;
    const int e = threadIdx.x;   // 0..255 == EDIM
    __shared__ float g[24];      // [t][8]
    __shared__ float gs[16];

    if (threadIdx.x < 24)
        g[threadIdx.x] = g_gate[(size_t)(threadIdx.x >> 3) * BATCH * 8
                                + (size_t)b * 8 + (threadIdx.x & 7)];
    if (threadIdx.x >= 32 && threadIdx.x < 48)
        gs[threadIdx.x - 32] = g_gsh[(size_t)b * 16 + (threadIdx.x - 32)];
    __syncthreads();

    float a0 = 0.0f, a1 = 0.0f, a2 = 0.0f, a3 = 0.0f;
    const float* eo = g_eo + (size_t)b * EDIM + e;

    #pragma unroll
    for (int j = 0; j < 12; j++) {
        float v = eo[(size_t)j * BATCH * EDIM];
        const int t = j >> 2;
        float gw = g[t * 8 + (j & 3)];
        if (t == 0)      a0 += gw * v;
        else if (t == 1) a1 += gw * v;
        else             a2 += gw * v;
        a3 += gs[j] * v;
    }
    #pragma unroll
    for (int s = 0; s < 4; s++) {
        float v = eo[(size_t)(12 + s) * BATCH * EDIM];
        a0 += g[0 * 8 + 4 + s] * v;
        a1 += g[1 * 8 + 4 + s] * v;
        a2 += g[2 * 8 + 4 + s] * v;
        a3 += gs[12 + s] * v;
    }

    const size_t o = (size_t)b * EDIM + e;
    const size_t plane = (size_t)BATCH * EDIM;
    out[o]             = a0;
    out[plane + o]     = a1;
    out[2 * plane + o] = a2;
    out[3 * plane + o] = a3;
}

// ============================================================================
extern "C" void kernel_launch(void* const* d_in, const int* in_sizes, int n_in,
                              void* d_out, int out_size)
{
    const float* x_tasks  = (const float*)d_in[0];
    const float* x_shared = (const float*)d_in[1];
    const float* W_spec1  = (const float*)d_in[2];
    const float* b_spec1  = (const float*)d_in[3];
    const float* W_spec2  = (const float*)d_in[4];
    const float* b_spec2  = (const float*)d_in[5];
    const float* W_sh1    = (const float*)d_in[6];
    const float* b_sh1    = (const float*)d_in[7];
    const float* W_sh2    = (const float*)d_in[8];
    const float* b_sh2    = (const float*)d_in[9];
    const float* W_gate   = (const float*)d_in[10];
    const float* b_gate   = (const float*)d_in[11];
    const float* W_gsh    = (const float*)d_in[12];
    const float* b_gsh    = (const float*)d_in[13];
    float* out = (float*)d_out;

    l1_kernel<<<dim3(HID / 128, BATCH / 128, NEXP), 256>>>(
        x_tasks, x_shared, W_spec1, b_spec1, W_sh1, b_sh1);
    l2_kernel<<<dim3(EDIM / 128, BATCH / 128, NEXP), 256>>>(
        W_spec2, b_spec2, W_sh2, b_sh2);
    gates_kernel<<<(4 * BATCH) / 8, 256>>>(
        x_tasks, x_shared, W_gate, b_gate, W_gsh, b_gsh);
    combine_kernel<<<BATCH, 256>>>(out);
}

// round 3
// speedup vs baseline: 1.9792x; 1.9792x over previous
#include <cuda_runtime.h>
#include <cuda_bf16.h>
#include <cstdint>
#include <math.h>

#define BATCH 8192
#define DIM   1024
#define HID   512
#define EDIM  256
#define NEXP  16
#define TTASK 3

// ---------------- device scratch (no allocations allowed) ----------------
__device__ __nv_bfloat16 g_xhi[(size_t)4 * BATCH * DIM];
__device__ __nv_bfloat16 g_xlo[(size_t)4 * BATCH * DIM];
__device__ __nv_bfloat16 g_w1hi[(size_t)NEXP * HID * DIM];   // [e][H][D] K-major
__device__ __nv_bfloat16 g_w1lo[(size_t)NEXP * HID * DIM];
__device__ __nv_bfloat16 g_w2hi[(size_t)NEXP * EDIM * HID];  // [e][E][H] K-major
__device__ __nv_bfloat16 g_w2lo[(size_t)NEXP * EDIM * HID];
__device__ __nv_bfloat16 g_hhi[(size_t)NEXP * BATCH * HID];
__device__ __nv_bfloat16 g_hlo[(size_t)NEXP * BATCH * HID];
__device__ float g_eo [(size_t)NEXP * BATCH * EDIM];
__device__ float g_gate[(size_t)TTASK * BATCH * 8];
__device__ float g_gsh [(size_t)BATCH * 16];

// ---------------- low-level helpers (all sm_80-portable) ----------------
__device__ __forceinline__ uint32_t smem_u32(const void* p) {
    uint32_t a;
    asm("{ .reg .u64 t; cvta.to.shared.u64 t, %1; cvt.u32.u64 %0, t; }" : "=r"(a) : "l"(p));
    return a;
}
__device__ __forceinline__ void cp16(uint32_t s, const void* g) {
    asm volatile("cp.async.cg.shared.global [%0], [%1], 16;" :: "r"(s), "l"(g));
}
#define CP_COMMIT() asm volatile("cp.async.commit_group;" ::: "memory")
#define CP_WAIT2()  asm volatile("cp.async.wait_group 2;"  ::: "memory")

__device__ __forceinline__ void ldsm4(uint32_t (&r)[4], uint32_t a) {
    asm volatile("ldmatrix.sync.aligned.m8n8.x4.shared.b16 {%0,%1,%2,%3}, [%4];"
                 : "=r"(r[0]), "=r"(r[1]), "=r"(r[2]), "=r"(r[3]) : "r"(a));
}
__device__ __forceinline__ void mma_bf16(float (&c)[4], const uint32_t (&a)[4],
                                         uint32_t b0, uint32_t b1) {
    asm volatile("mma.sync.aligned.m16n8k16.row.col.f32.bf16.bf16.f32 "
                 "{%0,%1,%2,%3}, {%4,%5,%6,%7}, {%8,%9}, {%0,%1,%2,%3};"
                 : "+f"(c[0]), "+f"(c[1]), "+f"(c[2]), "+f"(c[3])
                 : "r"(a[0]), "r"(a[1]), "r"(a[2]), "r"(a[3]), "r"(b0), "r"(b1));
}
__device__ __forceinline__ uint32_t pk2(float a, float b) {
    __nv_bfloat162 t = __floats2bfloat162_rn(a, b);
    return *reinterpret_cast<uint32_t*>(&t);
}

// ---------------- GEMM geometry ----------------
// BM=128, BN=128, BK=32 (bf16). SMEM rows padded to 80B (conflict-free ldmatrix).
#define RS       80u
#define OP_SZ    (128u * RS)          // 10240 B per operand tile
#define OFF_ALO  OP_SZ
#define OFF_BHI  (2u * OP_SZ)
#define OFF_BLO  (3u * OP_SZ)
#define STG_SZ   (4u * OP_SZ)         // 40960 B per stage
#define NSTG     4
#define BIAS_OFF (NSTG * STG_SZ)      // 163840
#define SMEM_TT  (BIAS_OFF + 512)     // +128 floats bias

// Y[128,128] tile of relu(A @ B^T + bias); A=[rows,K] K-major hi/lo, B=[N,K] hi/lo.
// 3-MMA bf16 split: hi*hi + hi*lo + lo*hi.
template<int K, int OUTN, bool SPLIT_OUT>
__global__ void __launch_bounds__(256, 1) gemm_kernel(
    const __nv_bfloat16* __restrict__ Ahi, const __nv_bfloat16* __restrict__ Alo,
    const __nv_bfloat16* __restrict__ Bhi, const __nv_bfloat16* __restrict__ Blo,
    const float* __restrict__ bias_spec,   const float* __restrict__ bias_sh)
{
    constexpr int KIT = K / 32;
    extern __shared__ __align__(16) char smem[];
    const uint32_t sb = smem_u32(smem);
    const int tid = threadIdx.x;
    const int e  = blockIdx.z;
    const int bm = blockIdx.y * 128;
    const int bn = blockIdx.x * 128;
    const int zA = SPLIT_OUT ? (e < 12 ? (e >> 2) : 3) : e;

    float* bias_sm = (float*)(smem + BIAS_OFF);
    if (tid < 128) {
        const float* bias = (e < 12) ? bias_spec + (size_t)e * OUTN
                                     : bias_sh  + (size_t)(e - 12) * OUTN;
        bias_sm[tid] = bias[bn + tid];
    }

    const __nv_bfloat16* gAh = Ahi + ((size_t)zA * BATCH + bm) * K;
    const __nv_bfloat16* gAl = Alo + ((size_t)zA * BATCH + bm) * K;
    const __nv_bfloat16* gBh = Bhi + ((size_t)e * OUTN + bn) * K;
    const __nv_bfloat16* gBl = Blo + ((size_t)e * OUTN + bn) * K;

    const int lr = tid >> 1;          // 0..127 row
    const int lc = (tid & 1) * 2;     // 16B-chunk 0 or 2

    auto load_stage = [&](int s, int k0) {
        uint32_t st = sb + (uint32_t)s * STG_SZ + (uint32_t)lr * RS + (uint32_t)lc * 16;
        size_t go = (size_t)lr * K + k0 + lc * 8;
        cp16(st,               gAh + go); cp16(st + 16,           gAh + go + 8);
        cp16(st + OFF_ALO,     gAl + go); cp16(st + OFF_ALO + 16, gAl + go + 8);
        cp16(st + OFF_BHI,     gBh + go); cp16(st + OFF_BHI + 16, gBh + go + 8);
        cp16(st + OFF_BLO,     gBl + go); cp16(st + OFF_BLO + 16, gBl + go + 8);
        CP_COMMIT();
    };

    load_stage(0, 0);
    load_stage(1, 32);
    load_stage(2, 64);

    const int wid = tid >> 5, L = tid & 31;
    const int mbase = (wid >> 2) * 64;   // warp row block (0,64)
    const int nbase = (wid & 3) * 32;    // warp col block (0,32,64,96)

    float acc[4][4][4];
    #pragma unroll
    for (int i = 0; i < 4; i++)
        #pragma unroll
        for (int j = 0; j < 4; j++)
            #pragma unroll
            for (int q = 0; q < 4; q++) acc[i][j][q] = 0.0f;

    // ldmatrix lane address offsets (within a stage, before k-step shift)
    const uint32_t aoff = (uint32_t)(mbase + (L & 15)) * RS + (uint32_t)(((L >> 4) & 1) * 16);
    const uint32_t boff = (uint32_t)(nbase + (L & 7) + ((L >> 4) & 1) * 8) * RS
                        + (uint32_t)(((L >> 3) & 1) * 16);

    for (int kt = 0; kt < KIT; kt++) {
        CP_WAIT2();
        __syncthreads();
        if (kt + 3 < KIT) load_stage((kt + 3) & 3, (kt + 3) * 32);
        else              CP_COMMIT();   // keep group window sliding for WAIT2

        const uint32_t sbase = sb + (uint32_t)(kt & 3) * STG_SZ;
        #pragma unroll
        for (int ks = 0; ks < 2; ks++) {
            uint32_t ah[4][4], al[4][4], bh[2][4], bl[2][4];
            const uint32_t ka = sbase + aoff + ks * 32;
            #pragma unroll
            for (int mt = 0; mt < 4; mt++) {
                ldsm4(ah[mt], ka + mt * (16 * RS));
                ldsm4(al[mt], ka + OFF_ALO + mt * (16 * RS));
            }
            const uint32_t kb = sbase + OFF_BHI + boff + ks * 32;
            #pragma unroll
            for (int nt2 = 0; nt2 < 2; nt2++) {
                ldsm4(bh[nt2], kb + nt2 * (16 * RS));
                ldsm4(bl[nt2], kb + (OFF_BLO - OFF_BHI) + nt2 * (16 * RS));
            }
            #pragma unroll
            for (int mt = 0; mt < 4; mt++)
                #pragma unroll
                for (int nt = 0; nt < 4; nt++) {
                    const uint32_t b0h = bh[nt >> 1][(nt & 1) * 2];
                    const uint32_t b1h = bh[nt >> 1][(nt & 1) * 2 + 1];
                    const uint32_t b0l = bl[nt >> 1][(nt & 1) * 2];
                    const uint32_t b1l = bl[nt >> 1][(nt & 1) * 2 + 1];
                    mma_bf16(acc[mt][nt], ah[mt], b0h, b1h);
                    mma_bf16(acc[mt][nt], ah[mt], b0l, b1l);
                    mma_bf16(acc[mt][nt], al[mt], b0h, b1h);
                }
        }
    }

    // ---------------- epilogue: bias + relu, write out ----------------
    const int g  = L >> 2;
    const int t2 = (L & 3) * 2;
    #pragma unroll
    for (int mt = 0; mt < 4; mt++) {
        const int r0 = bm + mbase + mt * 16 + g;
        #pragma unroll
        for (int nt = 0; nt < 4; nt++) {
            const int col = nbase + nt * 8 + t2;     // local 0..127
            const float b0v = bias_sm[col], b1v = bias_sm[col + 1];
            float v00 = fmaxf(acc[mt][nt][0] + b0v, 0.0f);
            float v01 = fmaxf(acc[mt][nt][1] + b1v, 0.0f);
            float v10 = fmaxf(acc[mt][nt][2] + b0v, 0.0f);
            float v11 = fmaxf(acc[mt][nt][3] + b1v, 0.0f);
            if (SPLIT_OUT) {
                const size_t o0 = ((size_t)e * BATCH + r0) * OUTN + bn + col;
                const size_t o1 = o0 + (size_t)8 * OUTN;
                float h00 = __bfloat162float(__float2bfloat16_rn(v00));
                float h01 = __bfloat162float(__float2bfloat16_rn(v01));
                float h10 = __bfloat162float(__float2bfloat16_rn(v10));
                float h11 = __bfloat162float(__float2bfloat16_rn(v11));
                *reinterpret_cast<uint32_t*>(&g_hhi[o0]) = pk2(h00, h01);
                *reinterpret_cast<uint32_t*>(&g_hlo[o0]) = pk2(v00 - h00, v01 - h01);
                *reinterpret_cast<uint32_t*>(&g_hhi[o1]) = pk2(h10, h11);
                *reinterpret_cast<uint32_t*>(&g_hlo[o1]) = pk2(v10 - h10, v11 - h11);
            } else {
                const size_t o0 = ((size_t)e * BATCH + r0) * OUTN + bn + col;
                const size_t o1 = o0 + (size_t)8 * OUTN;
                *reinterpret_cast<float2*>(&g_eo[o0]) = make_float2(v00, v01);
                *reinterpret_cast<float2*>(&g_eo[o1]) = make_float2(v10, v11);
            }
        }
    }
}

// ---------------- input split: fp32 -> bf16 hi/lo ----------------
__global__ __launch_bounds__(256) void convert_x_kernel(
    const float* __restrict__ xt, const float* __restrict__ xs)
{
    const size_t i = (size_t)blockIdx.x * blockDim.x + threadIdx.x;
    const size_t base = i * 4;
    const size_t T3 = (size_t)3 * BATCH * DIM;
    float4 v = (base < T3) ? *(const float4*)(xt + base)
                           : *(const float4*)(xs + base - T3);
    float h0 = __bfloat162float(__float2bfloat16_rn(v.x));
    float h1 = __bfloat162float(__float2bfloat16_rn(v.y));
    float h2 = __bfloat162float(__float2bfloat16_rn(v.z));
    float h3 = __bfloat162float(__float2bfloat16_rn(v.w));
    uint2 H = { pk2(h0, h1), pk2(h2, h3) };
    uint2 L = { pk2(v.x - h0, v.y - h1), pk2(v.z - h2, v.w - h3) };
    *reinterpret_cast<uint2*>(&g_xhi[base]) = H;
    *reinterpret_cast<uint2*>(&g_xlo[base]) = L;
}

// ---------------- weight transpose + split: [e][K][N] -> [e][N][K] bf16 hi/lo ----
__global__ __launch_bounds__(256) void wtrans_kernel(
    const float* __restrict__ Wsp, const float* __restrict__ Wsh,
    __nv_bfloat16* __restrict__ dhi, __nv_bfloat16* __restrict__ dlo,
    int K, int N)
{
    __shared__ float t[32][33];
    const int e = blockIdx.z;
    const float* src = (e < 12) ? Wsp + (size_t)e * K * N
                                : Wsh + (size_t)(e - 12) * K * N;
    const int n0 = blockIdx.x * 32, k0 = blockIdx.y * 32;
    const int c = threadIdx.x & 31, r8 = threadIdx.x >> 5;
    #pragma unroll
    for (int rr = 0; rr < 32; rr += 8)
        t[r8 + rr][c] = src[(size_t)(k0 + r8 + rr) * N + n0 + c];
    __syncthreads();
    #pragma unroll
    for (int rr = 0; rr < 32; rr += 8) {
        float v = t[c][r8 + rr];
        size_t o = ((size_t)e * N + n0 + r8 + rr) * K + k0 + c;
        __nv_bfloat16 hb = __float2bfloat16_rn(v);
        dhi[o] = hb;
        dlo[o] = __float2bfloat16_rn(v - __bfloat162float(hb));
    }
}

// ---------------- gates ----------------
__global__ __launch_bounds__(256) void gates_kernel(
    const float* __restrict__ x_tasks, const float* __restrict__ x_shared,
    const float* __restrict__ W_gate,  const float* __restrict__ b_gate,
    const float* __restrict__ W_gsh,   const float* __restrict__ b_gsh)
{
    const int warp = (blockIdx.x * blockDim.x + threadIdx.x) >> 5;
    const int lane = threadIdx.x & 31;
    const int t = warp >> 13;
    const int b = warp & (BATCH - 1);

    if (t < TTASK) {
        const float* x = x_tasks + ((size_t)t * BATCH + b) * DIM;
        const float* W = W_gate + (size_t)t * DIM * 8;
        float s[8] = {0,0,0,0,0,0,0,0};
        for (int d = lane; d < DIM; d += 32) {
            float xv = x[d];
            float4 w0 = *(const float4*)(W + (size_t)d * 8);
            float4 w1 = *(const float4*)(W + (size_t)d * 8 + 4);
            s[0] += xv * w0.x; s[1] += xv * w0.y; s[2] += xv * w0.z; s[3] += xv * w0.w;
            s[4] += xv * w1.x; s[5] += xv * w1.y; s[6] += xv * w1.z; s[7] += xv * w1.w;
        }
        #pragma unroll
        for (int o = 0; o < 8; o++)
            #pragma unroll
            for (int off = 16; off > 0; off >>= 1)
                s[o] += __shfl_xor_sync(0xffffffffu, s[o], off);
        if (lane == 0) {
            float mx = -1e30f;
            #pragma unroll
            for (int o = 0; o < 8; o++) { s[o] += b_gate[t * 8 + o]; mx = fmaxf(mx, s[o]); }
            float sum = 0.0f;
            #pragma unroll
            for (int o = 0; o < 8; o++) { s[o] = expf(s[o] - mx); sum += s[o]; }
            float inv = 1.0f / sum;
            #pragma unroll
            for (int o = 0; o < 8; o++)
                g_gate[((size_t)t * BATCH + b) * 8 + o] = s[o] * inv;
        }
    } else {
        const float* x = x_shared + (size_t)b * DIM;
        float s[16];
        #pragma unroll
        for (int o = 0; o < 16; o++) s[o] = 0.0f;
        for (int d = lane; d < DIM; d += 32) {
            float xv = x[d];
            float4 w0 = *(const float4*)(W_gsh + (size_t)d * 16);
            float4 w1 = *(const float4*)(W_gsh + (size_t)d * 16 + 4);
            float4 w2 = *(const float4*)(W_gsh + (size_t)d * 16 + 8);
            float4 w3 = *(const float4*)(W_gsh + (size_t)d * 16 + 12);
            s[ 0] += xv * w0.x; s[ 1] += xv * w0.y; s[ 2] += xv * w0.z; s[ 3] += xv * w0.w;
            s[ 4] += xv * w1.x; s[ 5] += xv * w1.y; s[ 6] += xv * w1.z; s[ 7] += xv * w1.w;
            s[ 8] += xv * w2.x; s[ 9] += xv * w2.y; s[10] += xv * w2.z; s[11] += xv * w2.w;
            s[12] += xv * w3.x; s[13] += xv * w3.y; s[14] += xv * w3.z; s[15] += xv * w3.w;
        }
        #pragma unroll
        for (int o = 0; o < 16; o++)
            #pragma unroll
            for (int off = 16; off > 0; off >>= 1)
                s[o] += __shfl_xor_sync(0xffffffffu, s[o], off);
        if (lane == 0) {
            float mx = -1e30f;
            #pragma unroll
            for (int o = 0; o < 16; o++) { s[o] += b_gsh[o]; mx = fmaxf(mx, s[o]); }
            float sum = 0.0f;
            #pragma unroll
            for (int o = 0; o < 16; o++) { s[o] = expf(s[o] - mx); sum += s[o]; }
            float inv = 1.0f / sum;
            #pragma unroll
            for (int o = 0; o < 16; o++)
                g_gsh[(size_t)b * 16 + o] = s[o] * inv;
        }
    }
}

// ---------------- combine ----------------
__global__ __launch_bounds__(256) void combine_kernel(float* __restrict__ out)
{
    const int b = blockIdx.x;
    const int e = threadIdx.x;
    __shared__ float g[24];
    __shared__ float gs[16];

    if (threadIdx.x < 24)
        g[threadIdx.x] = g_gate[(size_t)(threadIdx.x >> 3) * BATCH * 8
                                + (size_t)b * 8 + (threadIdx.x & 7)];
    if (threadIdx.x >= 32 && threadIdx.x < 48)
        gs[threadIdx.x - 32] = g_gsh[(size_t)b * 16 + (threadIdx.x - 32)];
    __syncthreads();

    float a0 = 0.0f, a1 = 0.0f, a2 = 0.0f, a3 = 0.0f;
    const float* eo = g_eo + (size_t)b * EDIM + e;

    #pragma unroll
    for (int j = 0; j < 12; j++) {
        float v = eo[(size_t)j * BATCH * EDIM];
        const int t = j >> 2;
        float gw = g[t * 8 + (j & 3)];
        if (t == 0)      a0 += gw * v;
        else if (t == 1) a1 += gw * v;
        else             a2 += gw * v;
        a3 += gs[j] * v;
    }
    #pragma unroll
    for (int s = 0; s < 4; s++) {
        float v = eo[(size_t)(12 + s) * BATCH * EDIM];
        a0 += g[0 * 8 + 4 + s] * v;
        a1 += g[1 * 8 + 4 + s] * v;
        a2 += g[2 * 8 + 4 + s] * v;
        a3 += gs[12 + s] * v;
    }

    const size_t o = (size_t)b * EDIM + e;
    const size_t plane = (size_t)BATCH * EDIM;
    out[o]             = a0;
    out[plane + o]     = a1;
    out[2 * plane + o] = a2;
    out[3 * plane + o] = a3;
}

// ---------------- host ----------------
extern "C" void kernel_launch(void* const* d_in, const int* in_sizes, int n_in,
                              void* d_out, int out_size)
{
    const float* x_tasks  = (const float*)d_in[0];
    const float* x_shared = (const float*)d_in[1];
    const float* W_spec1  = (const float*)d_in[2];
    const float* b_spec1  = (const float*)d_in[3];
    const float* W_spec2  = (const float*)d_in[4];
    const float* b_spec2  = (const float*)d_in[5];
    const float* W_sh1    = (const float*)d_in[6];
    const float* b_sh1    = (const float*)d_in[7];
    const float* W_sh2    = (const float*)d_in[8];
    const float* b_sh2    = (const float*)d_in[9];
    const float* W_gate   = (const float*)d_in[10];
    const float* b_gate   = (const float*)d_in[11];
    const float* W_gsh    = (const float*)d_in[12];
    const float* b_gsh    = (const float*)d_in[13];
    float* out = (float*)d_out;

    void *p_xhi, *p_xlo, *p_w1hi, *p_w1lo, *p_w2hi, *p_w2lo, *p_hhi, *p_hlo;
    cudaGetSymbolAddress(&p_xhi, g_xhi);   cudaGetSymbolAddress(&p_xlo, g_xlo);
    cudaGetSymbolAddress(&p_w1hi, g_w1hi); cudaGetSymbolAddress(&p_w1lo, g_w1lo);
    cudaGetSymbolAddress(&p_w2hi, g_w2hi); cudaGetSymbolAddress(&p_w2lo, g_w2lo);
    cudaGetSymbolAddress(&p_hhi, g_hhi);   cudaGetSymbolAddress(&p_hlo, g_hlo);

    cudaFuncSetAttribute(gemm_kernel<1024, HID, true>,
                         cudaFuncAttributeMaxDynamicSharedMemorySize, SMEM_TT);
    cudaFuncSetAttribute(gemm_kernel<512, EDIM, false>,
                         cudaFuncAttributeMaxDynamicSharedMemorySize, SMEM_TT);

    // prep: split inputs/weights into bf16 hi/lo (weights also transposed to [N,K])
    convert_x_kernel<<<(4u * BATCH * DIM / 4) / 256, 256>>>(x_tasks, x_shared);
    wtrans_kernel<<<dim3(HID / 32, DIM / 32, NEXP), 256>>>(
        W_spec1, W_sh1, (__nv_bfloat16*)p_w1hi, (__nv_bfloat16*)p_w1lo, DIM, HID);
    wtrans_kernel<<<dim3(EDIM / 32, HID / 32, NEXP), 256>>>(
        W_spec2, W_sh2, (__nv_bfloat16*)p_w2hi, (__nv_bfloat16*)p_w2lo, HID, EDIM);

    gates_kernel<<<(4 * BATCH) / 8, 256>>>(
        x_tasks, x_shared, W_gate, b_gate, W_gsh, b_gsh);

    gemm_kernel<1024, HID, true><<<dim3(HID / 128, BATCH / 128, NEXP), 256, SMEM_TT>>>(
        (const __nv_bfloat16*)p_xhi, (const __nv_bfloat16*)p_xlo,
        (const __nv_bfloat16*)p_w1hi, (const __nv_bfloat16*)p_w1lo, b_spec1, b_sh1);
    gemm_kernel<512, EDIM, false><<<dim3(EDIM / 128, BATCH / 128, NEXP), 256, SMEM_TT>>>(
        (const __nv_bfloat16*)p_hhi, (const __nv_bfloat16*)p_hlo,
        (const __nv_bfloat16*)p_w2hi, (const __nv_bfloat16*)p_w2lo, b_spec2, b_sh2);

    combine_kernel<<<BATCH, 256>>>(out);
}

// round 5
// speedup vs baseline: 4.1318x; 2.0876x over previous
#include <cuda_runtime.h>
#include <cuda_bf16.h>
#include <cuda_fp16.h>
#include <cstdint>
#include <math.h>

#define BATCH 8192
#define DIM   1024
#define HID   512
#define EDIM  256
#define NEXP  16
#define TTASK 3

// ---------------- device scratch (no allocations allowed) ----------------
__device__ __half g_xh[(size_t)4 * BATCH * DIM];            // inputs fp16 (4 planes: 3 task + shared)
__device__ __half g_w1[(size_t)NEXP * HID * DIM];           // [e][H][D] K-major fp16
__device__ __half g_w2[(size_t)NEXP * EDIM * HID];          // [e][E][H] K-major fp16
__device__ __half g_h [(size_t)NEXP * BATCH * HID];         // layer-1 activations fp16
__device__ float  g_eo[(size_t)NEXP * BATCH * EDIM];
__device__ float  g_gate[(size_t)TTASK * BATCH * 8];
__device__ float  g_gsh [(size_t)BATCH * 16];

// ---------------- low-level helpers ----------------
__device__ __forceinline__ uint32_t smem_u32(const void* p) {
    uint32_t a;
    asm("{ .reg .u64 t; cvta.to.shared.u64 t, %1; cvt.u32.u64 %0, t; }" : "=r"(a) : "l"(p));
    return a;
}
__device__ __forceinline__ void cp16(uint32_t s, const void* g) {
    asm volatile("cp.async.cg.shared.global [%0], [%1], 16;" :: "r"(s), "l"(g));
}
#define CP_COMMIT() asm volatile("cp.async.commit_group;" ::: "memory")
#define CP_WAIT2()  asm volatile("cp.async.wait_group 2;"  ::: "memory")

__device__ __forceinline__ void ldsm4(uint32_t (&r)[4], uint32_t a) {
    asm volatile("ldmatrix.sync.aligned.m8n8.x4.shared.b16 {%0,%1,%2,%3}, [%4];"
                 : "=r"(r[0]), "=r"(r[1]), "=r"(r[2]), "=r"(r[3]) : "r"(a));
}
__device__ __forceinline__ void mma_f16(float (&c)[4], const uint32_t (&a)[4],
                                        uint32_t b0, uint32_t b1) {
    asm volatile("mma.sync.aligned.m16n8k16.row.col.f32.f16.f16.f32 "
                 "{%0,%1,%2,%3}, {%4,%5,%6,%7}, {%8,%9}, {%0,%1,%2,%3};"
                 : "+f"(c[0]), "+f"(c[1]), "+f"(c[2]), "+f"(c[3])
                 : "r"(a[0]), "r"(a[1]), "r"(a[2]), "r"(a[3]), "r"(b0), "r"(b1));
}
__device__ __forceinline__ uint32_t pk2h(float a, float b) {
    __half2 t = __floats2half2_rn(a, b);
    return *reinterpret_cast<uint32_t*>(&t);
}

// ---------------- GEMM geometry ----------------
// BM=128, BN=128, BK=32 fp16. SMEM rows padded to 80B (conflict-free ldmatrix).
#define RS       80u
#define OP_SZ    (128u * RS)          // 10240 B per operand tile
#define OFF_B    OP_SZ
#define STG_SZ   (2u * OP_SZ)         // 20480 B per stage
#define NSTG     4
#define BIAS_OFF (NSTG * STG_SZ)      // 81920
#define SMEM_TT  (BIAS_OFF + 512)

// Y[128,128] tile of relu(A @ B^T + bias); A=[rows,K] K-major fp16, B=[N,K] fp16.
template<int K, int OUTN, bool SPLIT_OUT>
__global__ void __launch_bounds__(256, 1) gemm_kernel(
    const __half* __restrict__ A, const __half* __restrict__ B,
    const float* __restrict__ bias_spec, const float* __restrict__ bias_sh)
{
    constexpr int KIT = K / 32;
    extern __shared__ __align__(16) char smem[];
    const uint32_t sb = smem_u32(smem);
    const int tid = threadIdx.x;
    const int e  = blockIdx.z;
    const int bm = blockIdx.y * 128;
    const int bn = blockIdx.x * 128;
    const int zA = SPLIT_OUT ? (e < 12 ? (e >> 2) : 3) : e;

    float* bias_sm = (float*)(smem + BIAS_OFF);
    if (tid < 128) {
        const float* bias = (e < 12) ? bias_spec + (size_t)e * OUTN
                                     : bias_sh  + (size_t)(e - 12) * OUTN;
        bias_sm[tid] = bias[bn + tid];
    }

    const __half* gA = A + ((size_t)zA * BATCH + bm) * K;
    const __half* gB = B + ((size_t)e * OUTN + bn) * K;

    const int lr = tid >> 1;          // 0..127 row
    const int lc = tid & 1;           // 32B-half of 64B row

    auto load_stage = [&](int s, int k0) {
        uint32_t st = sb + (uint32_t)s * STG_SZ + (uint32_t)lr * RS + (uint32_t)lc * 32;
        size_t go = (size_t)lr * K + k0 + lc * 16;
        cp16(st,            gA + go); cp16(st + 16,         gA + go + 8);
        cp16(st + OFF_B,    gB + go); cp16(st + OFF_B + 16, gB + go + 8);
        CP_COMMIT();
    };

    load_stage(0, 0);
    load_stage(1, 32);
    load_stage(2, 64);

    const int wid = tid >> 5, L = tid & 31;
    const int mbase = (wid >> 2) * 64;   // warp row block (0,64)
    const int nbase = (wid & 3) * 32;    // warp col block (0,32,64,96)

    float acc[4][4][4];
    #pragma unroll
    for (int i = 0; i < 4; i++)
        #pragma unroll
        for (int j = 0; j < 4; j++)
            #pragma unroll
            for (int q = 0; q < 4; q++) acc[i][j][q] = 0.0f;

    const uint32_t aoff = (uint32_t)(mbase + (L & 15)) * RS + (uint32_t)(((L >> 4) & 1) * 16);
    const uint32_t boff = (uint32_t)(nbase + (L & 7) + ((L >> 4) & 1) * 8) * RS
                        + (uint32_t)(((L >> 3) & 1) * 16);

    for (int kt = 0; kt < KIT; kt++) {
        CP_WAIT2();
        __syncthreads();
        if (kt + 3 < KIT) load_stage((kt + 3) & 3, (kt + 3) * 32);
        else              CP_COMMIT();   // keep group window sliding for WAIT2

        const uint32_t sbase = sb + (uint32_t)(kt & 3) * STG_SZ;
        #pragma unroll
        for (int ks = 0; ks < 2; ks++) {
            uint32_t ah[4][4], bh[2][4];
            const uint32_t ka = sbase + aoff + ks * 32;
            #pragma unroll
            for (int mt = 0; mt < 4; mt++) ldsm4(ah[mt], ka + mt * (16 * RS));
            const uint32_t kb = sbase + OFF_B + boff + ks * 32;
            #pragma unroll
            for (int nt2 = 0; nt2 < 2; nt2++) ldsm4(bh[nt2], kb + nt2 * (16 * RS));
            #pragma unroll
            for (int mt = 0; mt < 4; mt++)
                #pragma unroll
                for (int nt = 0; nt < 4; nt++)
                    mma_f16(acc[mt][nt], ah[mt],
                            bh[nt >> 1][(nt & 1) * 2], bh[nt >> 1][(nt & 1) * 2 + 1]);
        }
    }

    // ---------------- epilogue: bias + relu ----------------
    const int g  = L >> 2;
    const int t2 = (L & 3) * 2;
    #pragma unroll
    for (int mt = 0; mt < 4; mt++) {
        const int r0 = bm + mbase + mt * 16 + g;
        #pragma unroll
        for (int nt = 0; nt < 4; nt++) {
            const int col = nbase + nt * 8 + t2;
            const float b0v = bias_sm[col], b1v = bias_sm[col + 1];
            float v00 = fmaxf(acc[mt][nt][0] + b0v, 0.0f);
            float v01 = fmaxf(acc[mt][nt][1] + b1v, 0.0f);
            float v10 = fmaxf(acc[mt][nt][2] + b0v, 0.0f);
            float v11 = fmaxf(acc[mt][nt][3] + b1v, 0.0f);
            const size_t o0 = ((size_t)e * BATCH + r0) * OUTN + bn + col;
            const size_t o1 = o0 + (size_t)8 * OUTN;
            if (SPLIT_OUT) {
                *reinterpret_cast<uint32_t*>(&g_h[o0]) = pk2h(v00, v01);
                *reinterpret_cast<uint32_t*>(&g_h[o1]) = pk2h(v10, v11);
            } else {
                *reinterpret_cast<float2*>(&g_eo[o0]) = make_float2(v00, v01);
                *reinterpret_cast<float2*>(&g_eo[o1]) = make_float2(v10, v11);
            }
        }
    }
}

// ---------------- input convert: fp32 -> fp16 ----------------
__global__ __launch_bounds__(256) void convert_x_kernel(
    const float* __restrict__ xt, const float* __restrict__ xs)
{
    const size_t i = (size_t)blockIdx.x * blockDim.x + threadIdx.x;
    const size_t base = i * 4;
    const size_t T3 = (size_t)3 * BATCH * DIM;
    float4 v = (base < T3) ? *(const float4*)(xt + base)
                           : *(const float4*)(xs + base - T3);
    uint2 H = { pk2h(v.x, v.y), pk2h(v.z, v.w) };
    *reinterpret_cast<uint2*>(&g_xh[base]) = H;
}

// ---------------- weight transpose + convert: [e][K][N] -> [e][N][K] fp16 ----
__global__ __launch_bounds__(256) void wtrans_kernel(
    const float* __restrict__ Wsp, const float* __restrict__ Wsh,
    __half* __restrict__ dst, int K, int N)
{
    __shared__ float t[32][33];
    const int e = blockIdx.z;
    const float* src = (e < 12) ? Wsp + (size_t)e * K * N
                                : Wsh + (size_t)(e - 12) * K * N;
    const int n0 = blockIdx.x * 32, k0 = blockIdx.y * 32;
    const int c = threadIdx.x & 31, r8 = threadIdx.x >> 5;
    #pragma unroll
    for (int rr = 0; rr < 32; rr += 8)
        t[r8 + rr][c] = src[(size_t)(k0 + r8 + rr) * N + n0 + c];
    __syncthreads();
    #pragma unroll
    for (int rr = 0; rr < 32; rr += 8) {
        float v = t[c][r8 + rr];
        size_t o = ((size_t)e * N + n0 + r8 + rr) * K + k0 + c;
        dst[o] = __float2half_rn(v);
    }
}

// ---------------- gates: 4 rows/warp (task), 2 rows/warp (shared) ----------------
#define TASK_WARPS (TTASK * BATCH / 4)   // 6144
#define SH_WARPS   (BATCH / 2)           // 4096
__global__ __launch_bounds__(256) void gates_kernel(
    const float* __restrict__ x_tasks, const float* __restrict__ x_shared,
    const float* __restrict__ W_gate,  const float* __restrict__ b_gate,
    const float* __restrict__ W_gsh,   const float* __restrict__ b_gsh)
{
    const int warp = (blockIdx.x * blockDim.x + threadIdx.x) >> 5;
    const int lane = threadIdx.x & 31;

    if (warp < TASK_WARPS) {
        const int r0 = warp * 4;
        const int t  = r0 >> 13;
        const int b0 = r0 & (BATCH - 1);
        const float* x = x_tasks + ((size_t)t * BATCH + b0) * DIM;
        const float* W = W_gate + (size_t)t * DIM * 8;
        float s[4][8];
        #pragma unroll
        for (int r = 0; r < 4; r++)
            #pragma unroll
            for (int o = 0; o < 8; o++) s[r][o] = 0.0f;
        for (int d = lane; d < DIM; d += 32) {
            float4 w0 = *(const float4*)(W + (size_t)d * 8);
            float4 w1 = *(const float4*)(W + (size_t)d * 8 + 4);
            #pragma unroll
            for (int r = 0; r < 4; r++) {
                float xv = x[(size_t)r * DIM + d];
                s[r][0] += xv * w0.x; s[r][1] += xv * w0.y;
                s[r][2] += xv * w0.z; s[r][3] += xv * w0.w;
                s[r][4] += xv * w1.x; s[r][5] += xv * w1.y;
                s[r][6] += xv * w1.z; s[r][7] += xv * w1.w;
            }
        }
        #pragma unroll
        for (int r = 0; r < 4; r++)
            #pragma unroll
            for (int o = 0; o < 8; o++)
                #pragma unroll
                for (int off = 16; off > 0; off >>= 1)
                    s[r][o] += __shfl_xor_sync(0xffffffffu, s[r][o], off);
        if (lane == 0) {
            #pragma unroll
            for (int r = 0; r < 4; r++) {
                float mx = -1e30f;
                #pragma unroll
                for (int o = 0; o < 8; o++) { s[r][o] += b_gate[t * 8 + o]; mx = fmaxf(mx, s[r][o]); }
                float sum = 0.0f;
                #pragma unroll
                for (int o = 0; o < 8; o++) { s[r][o] = expf(s[r][o] - mx); sum += s[r][o]; }
                float inv = 1.0f / sum;
                #pragma unroll
                for (int o = 0; o < 8; o++)
                    g_gate[((size_t)t * BATCH + b0 + r) * 8 + o] = s[r][o] * inv;
            }
        }
    } else {
        const int b0 = (warp - TASK_WARPS) * 2;
        const float* x = x_shared + (size_t)b0 * DIM;
        float s[2][16];
        #pragma unroll
        for (int r = 0; r < 2; r++)
            #pragma unroll
            for (int o = 0; o < 16; o++) s[r][o] = 0.0f;
        for (int d = lane; d < DIM; d += 32) {
            float4 w0 = *(const float4*)(W_gsh + (size_t)d * 16);
            float4 w1 = *(const float4*)(W_gsh + (size_t)d * 16 + 4);
            float4 w2 = *(const float4*)(W_gsh + (size_t)d * 16 + 8);
            float4 w3 = *(const float4*)(W_gsh + (size_t)d * 16 + 12);
            #pragma unroll
            for (int r = 0; r < 2; r++) {
                float xv = x[(size_t)r * DIM + d];
                s[r][ 0] += xv * w0.x; s[r][ 1] += xv * w0.y; s[r][ 2] += xv * w0.z; s[r][ 3] += xv * w0.w;
                s[r][ 4] += xv * w1.x; s[r][ 5] += xv * w1.y; s[r][ 6] += xv * w1.z; s[r][ 7] += xv * w1.w;
                s[r][ 8] += xv * w2.x; s[r][ 9] += xv * w2.y; s[r][10] += xv * w2.z; s[r][11] += xv * w2.w;
                s[r][12] += xv * w3.x; s[r][13] += xv * w3.y; s[r][14] += xv * w3.z; s[r][15] += xv * w3.w;
            }
        }
        #pragma unroll
        for (int r = 0; r < 2; r++)
            #pragma unroll
            for (int o = 0; o < 16; o++)
                #pragma unroll
                for (int off = 16; off > 0; off >>= 1)
                    s[r][o] += __shfl_xor_sync(0xffffffffu, s[r][o], off);
        if (lane == 0) {
            #pragma unroll
            for (int r = 0; r < 2; r++) {
                float mx = -1e30f;
                #pragma unroll
                for (int o = 0; o < 16; o++) { s[r][o] += b_gsh[o]; mx = fmaxf(mx, s[r][o]); }
                float sum = 0.0f;
                #pragma unroll
                for (int o = 0; o < 16; o++) { s[r][o] = expf(s[r][o] - mx); sum += s[r][o]; }
                float inv = 1.0f / sum;
                #pragma unroll
                for (int o = 0; o < 16; o++)
                    g_gsh[(size_t)(b0 + r) * 16 + o] = s[r][o] * inv;
            }
        }
    }
}

// ---------------- combine ----------------
__global__ __launch_bounds__(256) void combine_kernel(float* __restrict__ out)
{
    const int b = blockIdx.x;
    const int e = threadIdx.x;
    __shared__ float g[24];
    __shared__ float gs[16];

    if (threadIdx.x < 24)
        g[threadIdx.x] = g_gate[(size_t)(threadIdx.x >> 3) * BATCH * 8
                                + (size_t)b * 8 + (threadIdx.x & 7)];
    if (threadIdx.x >= 32 && threadIdx.x < 48)
        gs[threadIdx.x - 32] = g_gsh[(size_t)b * 16 + (threadIdx.x - 32)];
    __syncthreads();

    float a0 = 0.0f, a1 = 0.0f, a2 = 0.0f, a3 = 0.0f;
    const float* eo = g_eo + (size_t)b * EDIM + e;

    #pragma unroll
    for (int j = 0; j < 12; j++) {
        float v = eo[(size_t)j * BATCH * EDIM];
        const int t = j >> 2;
        float gw = g[t * 8 + (j & 3)];
        if (t == 0)      a0 += gw * v;
        else if (t == 1) a1 += gw * v;
        else             a2 += gw * v;
        a3 += gs[j] * v;
    }
    #pragma unroll
    for (int s = 0; s < 4; s++) {
        float v = eo[(size_t)(12 + s) * BATCH * EDIM];
        a0 += g[0 * 8 + 4 + s] * v;
        a1 += g[1 * 8 + 4 + s] * v;
        a2 += g[2 * 8 + 4 + s] * v;
        a3 += gs[12 + s] * v;
    }

    const size_t o = (size_t)b * EDIM + e;
    const size_t plane = (size_t)BATCH * EDIM;
    out[o]             = a0;
    out[plane + o]     = a1;
    out[2 * plane + o] = a2;
    out[3 * plane + o] = a3;
}

// ---------------- host ----------------
extern "C" void kernel_launch(void* const* d_in, const int* in_sizes, int n_in,
                              void* d_out, int out_size)
{
    const float* x_tasks  = (const float*)d_in[0];
    const float* x_shared = (const float*)d_in[1];
    const float* W_spec1  = (const float*)d_in[2];
    const float* b_spec1  = (const float*)d_in[3];
    const float* W_spec2  = (const float*)d_in[4];
    const float* b_spec2  = (const float*)d_in[5];
    const float* W_sh1    = (const float*)d_in[6];
    const float* b_sh1    = (const float*)d_in[7];
    const float* W_sh2    = (const float*)d_in[8];
    const float* b_sh2    = (const float*)d_in[9];
    const float* W_gate   = (const float*)d_in[10];
    const float* b_gate   = (const float*)d_in[11];
    const float* W_gsh    = (const float*)d_in[12];
    const float* b_gsh    = (const float*)d_in[13];
    float* out = (float*)d_out;

    void *p_xh, *p_w1, *p_w2, *p_h;
    cudaGetSymbolAddress(&p_xh, g_xh);
    cudaGetSymbolAddress(&p_w1, g_w1);
    cudaGetSymbolAddress(&p_w2, g_w2);
    cudaGetSymbolAddress(&p_h, g_h);

    cudaFuncSetAttribute(gemm_kernel<1024, HID, true>,
                         cudaFuncAttributeMaxDynamicSharedMemorySize, SMEM_TT);
    cudaFuncSetAttribute(gemm_kernel<512, EDIM, false>,
                         cudaFuncAttributeMaxDynamicSharedMemorySize, SMEM_TT);

    convert_x_kernel<<<(4u * BATCH * DIM / 4) / 256, 256>>>(x_tasks, x_shared);
    wtrans_kernel<<<dim3(HID / 32, DIM / 32, NEXP), 256>>>(
        W_spec1, W_sh1, (__half*)p_w1, DIM, HID);
    wtrans_kernel<<<dim3(EDIM / 32, HID / 32, NEXP), 256>>>(
        W_spec2, W_sh2, (__half*)p_w2, HID, EDIM);

    gates_kernel<<<(TASK_WARPS + SH_WARPS) / 8, 256>>>(
        x_tasks, x_shared, W_gate, b_gate, W_gsh, b_gsh);

    gemm_kernel<1024, HID, true><<<dim3(HID / 128, BATCH / 128, NEXP), 256, SMEM_TT>>>(
        (const __half*)p_xh, (const __half*)p_w1, b_spec1, b_sh1);
    gemm_kernel<512, EDIM, false><<<dim3(EDIM / 128, BATCH / 128, NEXP), 256, SMEM_TT>>>(
        (const __half*)p_h, (const __half*)p_w2, b_spec2, b_sh2);

    combine_kernel<<<BATCH, 256>>>(out);
}

// round 6
// speedup vs baseline: 5.2555x; 1.2720x over previous
#include <cuda_runtime.h>
#include <cuda_bf16.h>
#include <cuda_fp16.h>
#include <cstdint>
#include <math.h>

#define BATCH 8192
#define DIM   1024
#define HID   512
#define EDIM  256
#define NEXP  16
#define TTASK 3

// ---------------- device scratch (no allocations allowed) ----------------
__device__ __half g_xh[(size_t)4 * BATCH * DIM];            // inputs fp16 (4 planes: 3 task + shared)
__device__ __half g_w1[(size_t)NEXP * HID * DIM];           // [e][H][D] K-major fp16
__device__ __half g_w2[(size_t)NEXP * EDIM * HID];          // [e][E][H] K-major fp16
__device__ __half g_h [(size_t)NEXP * BATCH * HID];         // layer-1 activations fp16
__device__ __half g_eo[(size_t)NEXP * BATCH * EDIM];        // expert outputs fp16
__device__ float  g_gate[(size_t)TTASK * BATCH * 8];
__device__ float  g_gsh [(size_t)BATCH * 16];

// ---------------- low-level helpers ----------------
__device__ __forceinline__ uint32_t smem_u32(const void* p) {
    uint32_t a;
    asm("{ .reg .u64 t; cvta.to.shared.u64 t, %1; cvt.u32.u64 %0, t; }" : "=r"(a) : "l"(p));
    return a;
}
__device__ __forceinline__ void cp16(uint32_t s, const void* g) {
    asm volatile("cp.async.cg.shared.global [%0], [%1], 16;" :: "r"(s), "l"(g));
}
#define CP_COMMIT() asm volatile("cp.async.commit_group;" ::: "memory")
#define CP_WAIT2()  asm volatile("cp.async.wait_group 2;"  ::: "memory")

__device__ __forceinline__ void ldsm4(uint32_t (&r)[4], uint32_t a) {
    asm volatile("ldmatrix.sync.aligned.m8n8.x4.shared.b16 {%0,%1,%2,%3}, [%4];"
                 : "=r"(r[0]), "=r"(r[1]), "=r"(r[2]), "=r"(r[3]) : "r"(a));
}
__device__ __forceinline__ void mma_f16(float (&c)[4], const uint32_t (&a)[4],
                                        uint32_t b0, uint32_t b1) {
    asm volatile("mma.sync.aligned.m16n8k16.row.col.f32.f16.f16.f32 "
                 "{%0,%1,%2,%3}, {%4,%5,%6,%7}, {%8,%9}, {%0,%1,%2,%3};"
                 : "+f"(c[0]), "+f"(c[1]), "+f"(c[2]), "+f"(c[3])
                 : "r"(a[0]), "r"(a[1]), "r"(a[2]), "r"(a[3]), "r"(b0), "r"(b1));
}
__device__ __forceinline__ uint32_t pk2h(float a, float b) {
    __half2 t = __floats2half2_rn(a, b);
    return *reinterpret_cast<uint32_t*>(&t);
}

// ---------------- GEMM geometry ----------------
// BM=128, BN=128, BK=32 fp16. SMEM rows padded to 80B (conflict-free ldmatrix).
#define RS       80u
#define OP_SZ    (128u * RS)          // 10240 B per operand tile
#define OFF_B    OP_SZ
#define STG_SZ   (2u * OP_SZ)         // 20480 B per stage
#define NSTG     4
#define BIAS_OFF (NSTG * STG_SZ)      // 81920
#define SMEM_TT  (BIAS_OFF + 512)

// Y[128,128] tile of relu(A @ B^T + bias); A=[rows,K] K-major fp16, B=[N,K] fp16.
template<int K, int OUTN, bool SPLIT_OUT>
__global__ void __launch_bounds__(256, 2) gemm_kernel(
    const __half* __restrict__ A, const __half* __restrict__ B,
    const float* __restrict__ bias_spec, const float* __restrict__ bias_sh)
{
    constexpr int KIT = K / 32;
    extern __shared__ __align__(16) char smem[];
    const uint32_t sb = smem_u32(smem);
    const int tid = threadIdx.x;
    const int e  = blockIdx.z;
    const int bm = blockIdx.y * 128;
    const int bn = blockIdx.x * 128;
    const int zA = SPLIT_OUT ? (e < 12 ? (e >> 2) : 3) : e;

    float* bias_sm = (float*)(smem + BIAS_OFF);
    if (tid < 128) {
        const float* bias = (e < 12) ? bias_spec + (size_t)e * OUTN
                                     : bias_sh  + (size_t)(e - 12) * OUTN;
        bias_sm[tid] = bias[bn + tid];
    }

    const __half* gA = A + ((size_t)zA * BATCH + bm) * K;
    const __half* gB = B + ((size_t)e * OUTN + bn) * K;

    const int lr = tid >> 1;          // 0..127 row
    const int lc = tid & 1;           // 32B-half of 64B row

    auto load_stage = [&](int s, int k0) {
        uint32_t st = sb + (uint32_t)s * STG_SZ + (uint32_t)lr * RS + (uint32_t)lc * 32;
        size_t go = (size_t)lr * K + k0 + lc * 16;
        cp16(st,            gA + go); cp16(st + 16,         gA + go + 8);
        cp16(st + OFF_B,    gB + go); cp16(st + OFF_B + 16, gB + go + 8);
        CP_COMMIT();
    };

    load_stage(0, 0);
    load_stage(1, 32);
    load_stage(2, 64);

    const int wid = tid >> 5, L = tid & 31;
    const int mbase = (wid >> 2) * 64;   // warp row block (0,64)
    const int nbase = (wid & 3) * 32;    // warp col block (0,32,64,96)

    float acc[4][4][4];
    #pragma unroll
    for (int i = 0; i < 4; i++)
        #pragma unroll
        for (int j = 0; j < 4; j++)
            #pragma unroll
            for (int q = 0; q < 4; q++) acc[i][j][q] = 0.0f;

    const uint32_t aoff = (uint32_t)(mbase + (L & 15)) * RS + (uint32_t)(((L >> 4) & 1) * 16);
    const uint32_t boff = (uint32_t)(nbase + (L & 7) + ((L >> 4) & 1) * 8) * RS
                        + (uint32_t)(((L >> 3) & 1) * 16);

    for (int kt = 0; kt < KIT; kt++) {
        CP_WAIT2();
        __syncthreads();
        if (kt + 3 < KIT) load_stage((kt + 3) & 3, (kt + 3) * 32);
        else              CP_COMMIT();   // keep group window sliding for WAIT2

        const uint32_t sbase = sb + (uint32_t)(kt & 3) * STG_SZ;
        #pragma unroll
        for (int ks = 0; ks < 2; ks++) {
            uint32_t ah[4][4], bh[2][4];
            const uint32_t ka = sbase + aoff + ks * 32;
            #pragma unroll
            for (int mt = 0; mt < 4; mt++) ldsm4(ah[mt], ka + mt * (16 * RS));
            const uint32_t kb = sbase + OFF_B + boff + ks * 32;
            #pragma unroll
            for (int nt2 = 0; nt2 < 2; nt2++) ldsm4(bh[nt2], kb + nt2 * (16 * RS));
            #pragma unroll
            for (int mt = 0; mt < 4; mt++)
                #pragma unroll
                for (int nt = 0; nt < 4; nt++)
                    mma_f16(acc[mt][nt], ah[mt],
                            bh[nt >> 1][(nt & 1) * 2], bh[nt >> 1][(nt & 1) * 2 + 1]);
        }
    }

    // ---------------- epilogue: bias + relu ----------------
    const int g  = L >> 2;
    const int t2 = (L & 3) * 2;
    #pragma unroll
    for (int mt = 0; mt < 4; mt++) {
        const int r0 = bm + mbase + mt * 16 + g;
        #pragma unroll
        for (int nt = 0; nt < 4; nt++) {
            const int col = nbase + nt * 8 + t2;
            const float b0v = bias_sm[col], b1v = bias_sm[col + 1];
            float v00 = fmaxf(acc[mt][nt][0] + b0v, 0.0f);
            float v01 = fmaxf(acc[mt][nt][1] + b1v, 0.0f);
            float v10 = fmaxf(acc[mt][nt][2] + b0v, 0.0f);
            float v11 = fmaxf(acc[mt][nt][3] + b1v, 0.0f);
            const size_t o0 = ((size_t)e * BATCH + r0) * OUTN + bn + col;
            const size_t o1 = o0 + (size_t)8 * OUTN;
            if (SPLIT_OUT) {
                *reinterpret_cast<uint32_t*>(&g_h[o0]) = pk2h(v00, v01);
                *reinterpret_cast<uint32_t*>(&g_h[o1]) = pk2h(v10, v11);
            } else {
                *reinterpret_cast<uint32_t*>(&g_eo[o0]) = pk2h(v00, v01);
                *reinterpret_cast<uint32_t*>(&g_eo[o1]) = pk2h(v10, v11);
            }
        }
    }
}

// ---------------- input convert: fp32 -> fp16 ----------------
__global__ __launch_bounds__(256) void convert_x_kernel(
    const float* __restrict__ xt, const float* __restrict__ xs)
{
    const size_t i = (size_t)blockIdx.x * blockDim.x + threadIdx.x;
    const size_t base = i * 4;
    const size_t T3 = (size_t)3 * BATCH * DIM;
    float4 v = (base < T3) ? *(const float4*)(xt + base)
                           : *(const float4*)(xs + base - T3);
    uint2 H = { pk2h(v.x, v.y), pk2h(v.z, v.w) };
    *reinterpret_cast<uint2*>(&g_xh[base]) = H;
}

// ---------------- weight transpose + convert: [e][K][N] -> [e][N][K] fp16 ----
__global__ __launch_bounds__(256) void wtrans_kernel(
    const float* __restrict__ Wsp, const float* __restrict__ Wsh,
    __half* __restrict__ dst, int K, int N)
{
    __shared__ float t[32][33];
    const int e = blockIdx.z;
    const float* src = (e < 12) ? Wsp + (size_t)e * K * N
                                : Wsh + (size_t)(e - 12) * K * N;
    const int n0 = blockIdx.x * 32, k0 = blockIdx.y * 32;
    const int c = threadIdx.x & 31, r8 = threadIdx.x >> 5;
    #pragma unroll
    for (int rr = 0; rr < 32; rr += 8)
        t[r8 + rr][c] = src[(size_t)(k0 + r8 + rr) * N + n0 + c];
    __syncthreads();
    #pragma unroll
    for (int rr = 0; rr < 32; rr += 8) {
        float v = t[c][r8 + rr];
        size_t o = ((size_t)e * N + n0 + r8 + rr) * K + k0 + c;
        dst[o] = __float2half_rn(v);
    }
}

// ---------------- gates: 4 rows/warp (task), 2 rows/warp (shared) ----------------
#define TASK_WARPS (TTASK * BATCH / 4)   // 6144
#define SH_WARPS   (BATCH / 2)           // 4096
__global__ __launch_bounds__(256) void gates_kernel(
    const float* __restrict__ x_tasks, const float* __restrict__ x_shared,
    const float* __restrict__ W_gate,  const float* __restrict__ b_gate,
    const float* __restrict__ W_gsh,   const float* __restrict__ b_gsh)
{
    const int warp = (blockIdx.x * blockDim.x + threadIdx.x) >> 5;
    const int lane = threadIdx.x & 31;

    if (warp < TASK_WARPS) {
        const int r0 = warp * 4;
        const int t  = r0 >> 13;
        const int b0 = r0 & (BATCH - 1);
        const float* x = x_tasks + ((size_t)t * BATCH + b0) * DIM;
        const float* W = W_gate + (size_t)t * DIM * 8;
        float s[4][8];
        #pragma unroll
        for (int r = 0; r < 4; r++)
            #pragma unroll
            for (int o = 0; o < 8; o++) s[r][o] = 0.0f;
        for (int d = lane; d < DIM; d += 32) {
            float4 w0 = *(const float4*)(W + (size_t)d * 8);
            float4 w1 = *(const float4*)(W + (size_t)d * 8 + 4);
            #pragma unroll
            for (int r = 0; r < 4; r++) {
                float xv = x[(size_t)r * DIM + d];
                s[r][0] += xv * w0.x; s[r][1] += xv * w0.y;
                s[r][2] += xv * w0.z; s[r][3] += xv * w0.w;
                s[r][4] += xv * w1.x; s[r][5] += xv * w1.y;
                s[r][6] += xv * w1.z; s[r][7] += xv * w1.w;
            }
        }
        #pragma unroll
        for (int r = 0; r < 4; r++)
            #pragma unroll
            for (int o = 0; o < 8; o++)
                #pragma unroll
                for (int off = 16; off > 0; off >>= 1)
                    s[r][o] += __shfl_xor_sync(0xffffffffu, s[r][o], off);
        if (lane == 0) {
            #pragma unroll
            for (int r = 0; r < 4; r++) {
                float mx = -1e30f;
                #pragma unroll
                for (int o = 0; o < 8; o++) { s[r][o] += b_gate[t * 8 + o]; mx = fmaxf(mx, s[r][o]); }
                float sum = 0.0f;
                #pragma unroll
                for (int o = 0; o < 8; o++) { s[r][o] = expf(s[r][o] - mx); sum += s[r][o]; }
                float inv = 1.0f / sum;
                #pragma unroll
                for (int o = 0; o < 8; o++)
                    g_gate[((size_t)t * BATCH + b0 + r) * 8 + o] = s[r][o] * inv;
            }
        }
    } else {
        const int b0 = (warp - TASK_WARPS) * 2;
        const float* x = x_shared + (size_t)b0 * DIM;
        float s[2][16];
        #pragma unroll
        for (int r = 0; r < 2; r++)
            #pragma unroll
            for (int o = 0; o < 16; o++) s[r][o] = 0.0f;
        for (int d = lane; d < DIM; d += 32) {
            float4 w0 = *(const float4*)(W_gsh + (size_t)d * 16);
            float4 w1 = *(const float4*)(W_gsh + (size_t)d * 16 + 4);
            float4 w2 = *(const float4*)(W_gsh + (size_t)d * 16 + 8);
            float4 w3 = *(const float4*)(W_gsh + (size_t)d * 16 + 12);
            #pragma unroll
            for (int r = 0; r < 2; r++) {
                float xv = x[(size_t)r * DIM + d];
                s[r][ 0] += xv * w0.x; s[r][ 1] += xv * w0.y; s[r][ 2] += xv * w0.z; s[r][ 3] += xv * w0.w;
                s[r][ 4] += xv * w1.x; s[r][ 5] += xv * w1.y; s[r][ 6] += xv * w1.z; s[r][ 7] += xv * w1.w;
                s[r][ 8] += xv * w2.x; s[r][ 9] += xv * w2.y; s[r][10] += xv * w2.z; s[r][11] += xv * w2.w;
                s[r][12] += xv * w3.x; s[r][13] += xv * w3.y; s[r][14] += xv * w3.z; s[r][15] += xv * w3.w;
            }
        }
        #pragma unroll
        for (int r = 0; r < 2; r++)
            #pragma unroll
            for (int o = 0; o < 16; o++)
                #pragma unroll
                for (int off = 16; off > 0; off >>= 1)
                    s[r][o] += __shfl_xor_sync(0xffffffffu, s[r][o], off);
        if (lane == 0) {
            #pragma unroll
            for (int r = 0; r < 2; r++) {
                float mx = -1e30f;
                #pragma unroll
                for (int o = 0; o < 16; o++) { s[r][o] += b_gsh[o]; mx = fmaxf(mx, s[r][o]); }
                float sum = 0.0f;
                #pragma unroll
                for (int o = 0; o < 16; o++) { s[r][o] = expf(s[r][o] - mx); sum += s[r][o]; }
                float inv = 1.0f / sum;
                #pragma unroll
                for (int o = 0; o < 16; o++)
                    g_gsh[(size_t)(b0 + r) * 16 + o] = s[r][o] * inv;
            }
        }
    }
}

// ---------------- combine (eo in fp16) ----------------
__global__ __launch_bounds__(256) void combine_kernel(float* __restrict__ out)
{
    const int b = blockIdx.x;
    const int e = threadIdx.x;
    __shared__ float g[24];
    __shared__ float gs[16];

    if (threadIdx.x < 24)
        g[threadIdx.x] = g_gate[(size_t)(threadIdx.x >> 3) * BATCH * 8
                                + (size_t)b * 8 + (threadIdx.x & 7)];
    if (threadIdx.x >= 32 && threadIdx.x < 48)
        gs[threadIdx.x - 32] = g_gsh[(size_t)b * 16 + (threadIdx.x - 32)];
    __syncthreads();

    float a0 = 0.0f, a1 = 0.0f, a2 = 0.0f, a3 = 0.0f;
    const __half* eo = g_eo + (size_t)b * EDIM + e;

    #pragma unroll
    for (int j = 0; j < 12; j++) {
        float v = __half2float(eo[(size_t)j * BATCH * EDIM]);
        const int t = j >> 2;
        float gw = g[t * 8 + (j & 3)];
        if (t == 0)      a0 += gw * v;
        else if (t == 1) a1 += gw * v;
        else             a2 += gw * v;
        a3 += gs[j] * v;
    }
    #pragma unroll
    for (int s = 0; s < 4; s++) {
        float v = __half2float(eo[(size_t)(12 + s) * BATCH * EDIM]);
        a0 += g[0 * 8 + 4 + s] * v;
        a1 += g[1 * 8 + 4 + s] * v;
        a2 += g[2 * 8 + 4 + s] * v;
        a3 += gs[12 + s] * v;
    }

    const size_t o = (size_t)b * EDIM + e;
    const size_t plane = (size_t)BATCH * EDIM;
    out[o]             = a0;
    out[plane + o]     = a1;
    out[2 * plane + o] = a2;
    out[3 * plane + o] = a3;
}

// ---------------- host ----------------
extern "C" void kernel_launch(void* const* d_in, const int* in_sizes, int n_in,
                              void* d_out, int out_size)
{
    const float* x_tasks  = (const float*)d_in[0];
    const float* x_shared = (const float*)d_in[1];
    const float* W_spec1  = (const float*)d_in[2];
    const float* b_spec1  = (const float*)d_in[3];
    const float* W_spec2  = (const float*)d_in[4];
    const float* b_spec2  = (const float*)d_in[5];
    const float* W_sh1    = (const float*)d_in[6];
    const float* b_sh1    = (const float*)d_in[7];
    const float* W_sh2    = (const float*)d_in[8];
    const float* b_sh2    = (const float*)d_in[9];
    const float* W_gate   = (const float*)d_in[10];
    const float* b_gate   = (const float*)d_in[11];
    const float* W_gsh    = (const float*)d_in[12];
    const float* b_gsh    = (const float*)d_in[13];
    float* out = (float*)d_out;

    void *p_xh, *p_w1, *p_w2, *p_h;
    cudaGetSymbolAddress(&p_xh, g_xh);
    cudaGetSymbolAddress(&p_w1, g_w1);
    cudaGetSymbolAddress(&p_w2, g_w2);
    cudaGetSymbolAddress(&p_h, g_h);

    cudaFuncSetAttribute(gemm_kernel<1024, HID, true>,
                         cudaFuncAttributeMaxDynamicSharedMemorySize, SMEM_TT);
    cudaFuncSetAttribute(gemm_kernel<512, EDIM, false>,
                         cudaFuncAttributeMaxDynamicSharedMemorySize, SMEM_TT);

    convert_x_kernel<<<(4u * BATCH * DIM / 4) / 256, 256>>>(x_tasks, x_shared);
    wtrans_kernel<<<dim3(HID / 32, DIM / 32, NEXP), 256>>>(
        W_spec1, W_sh1, (__half*)p_w1, DIM, HID);
    wtrans_kernel<<<dim3(EDIM / 32, HID / 32, NEXP), 256>>>(
        W_spec2, W_sh2, (__half*)p_w2, HID, EDIM);

    gates_kernel<<<(TASK_WARPS + SH_WARPS) / 8, 256>>>(
        x_tasks, x_shared, W_gate, b_gate, W_gsh, b_gsh);

    gemm_kernel<1024, HID, true><<<dim3(HID / 128, BATCH / 128, NEXP), 256, SMEM_TT>>>(
        (const __half*)p_xh, (const __half*)p_w1, b_spec1, b_sh1);
    gemm_kernel<512, EDIM, false><<<dim3(EDIM / 128, BATCH / 128, NEXP), 256, SMEM_TT>>>(
        (const __half*)p_h, (const __half*)p_w2, b_spec2, b_sh2);

    combine_kernel<<<BATCH, 256>>>(out);
}

// round 7
// speedup vs baseline: 5.3810x; 1.0239x over previous
#include <cuda_runtime.h>
#include <cuda_bf16.h>
#include <cuda_fp16.h>
#include <cstdint>
#include <math.h>

#define BATCH 8192
#define DIM   1024
#define HID   512
#define EDIM  256
#define NEXP  16
#define TTASK 3

// ---------------- device scratch (no allocations allowed) ----------------
__device__ __half g_xh[(size_t)4 * BATCH * DIM];            // inputs fp16 (4 planes: 3 task + shared)
__device__ __half g_w1[(size_t)NEXP * HID * DIM];           // [e][H][D] K-major fp16
__device__ __half g_w2[(size_t)NEXP * EDIM * HID];          // [e][E][H] K-major fp16
__device__ __half g_h [(size_t)NEXP * BATCH * HID];         // layer-1 activations fp16
__device__ __half g_eo[(size_t)NEXP * BATCH * EDIM];        // expert outputs fp16
__device__ float  g_gate[(size_t)TTASK * BATCH * 8];
__device__ float  g_gsh [(size_t)BATCH * 16];

// ---------------- low-level helpers ----------------
__device__ __forceinline__ uint32_t smem_u32(const void* p) {
    uint32_t a;
    asm("{ .reg .u64 t; cvta.to.shared.u64 t, %1; cvt.u32.u64 %0, t; }" : "=r"(a) : "l"(p));
    return a;
}
__device__ __forceinline__ void cp16(uint32_t s, const void* g) {
    asm volatile("cp.async.cg.shared.global [%0], [%1], 16;" :: "r"(s), "l"(g));
}
#define CP_COMMIT() asm volatile("cp.async.commit_group;" ::: "memory")
#define CP_WAIT2()  asm volatile("cp.async.wait_group 2;"  ::: "memory")

__device__ __forceinline__ void ldsm4(uint32_t (&r)[4], uint32_t a) {
    asm volatile("ldmatrix.sync.aligned.m8n8.x4.shared.b16 {%0,%1,%2,%3}, [%4];"
                 : "=r"(r[0]), "=r"(r[1]), "=r"(r[2]), "=r"(r[3]) : "r"(a));
}
__device__ __forceinline__ void mma_f16(float (&c)[4], const uint32_t (&a)[4],
                                        uint32_t b0, uint32_t b1) {
    asm volatile("mma.sync.aligned.m16n8k16.row.col.f32.f16.f16.f32 "
                 "{%0,%1,%2,%3}, {%4,%5,%6,%7}, {%8,%9}, {%0,%1,%2,%3};"
                 : "+f"(c[0]), "+f"(c[1]), "+f"(c[2]), "+f"(c[3])
                 : "r"(a[0]), "r"(a[1]), "r"(a[2]), "r"(a[3]), "r"(b0), "r"(b1));
}
__device__ __forceinline__ uint32_t pk2h(float a, float b) {
    __half2 t = __floats2half2_rn(a, b);
    return *reinterpret_cast<uint32_t*>(&t);
}

// ---------------- GEMM geometry ----------------
// BM=128, BN=128, BK=32 fp16. SMEM rows padded to 80B (conflict-free ldmatrix).
#define RS       80u
#define OP_SZ    (128u * RS)          // 10240 B per operand tile
#define OFF_B    OP_SZ
#define STG_SZ   (2u * OP_SZ)         // 20480 B per stage
#define NSTG     4
#define BIAS_OFF (NSTG * STG_SZ)      // 81920
#define SMEM_TT  (BIAS_OFF + 512)

// Y[128,128] tile of relu(A @ B^T + bias); A=[rows,K] K-major fp16, B=[N,K] fp16.
template<int K, int OUTN, bool SPLIT_OUT>
__global__ void __launch_bounds__(256, 2) gemm_kernel(
    const __half* __restrict__ A, const __half* __restrict__ B,
    const float* __restrict__ bias_spec, const float* __restrict__ bias_sh)
{
    constexpr int KIT = K / 32;
    extern __shared__ __align__(16) char smem[];
    const uint32_t sb = smem_u32(smem);
    const int tid = threadIdx.x;
    const int e  = blockIdx.z;
    const int bm = blockIdx.y * 128;
    const int bn = blockIdx.x * 128;
    const int zA = SPLIT_OUT ? (e < 12 ? (e >> 2) : 3) : e;

    float* bias_sm = (float*)(smem + BIAS_OFF);
    if (tid < 128) {
        const float* bias = (e < 12) ? bias_spec + (size_t)e * OUTN
                                     : bias_sh  + (size_t)(e - 12) * OUTN;
        bias_sm[tid] = bias[bn + tid];
    }

    const __half* gA = A + ((size_t)zA * BATCH + bm) * K;
    const __half* gB = B + ((size_t)e * OUTN + bn) * K;

    const int lr = tid >> 1;          // 0..127 row
    const int lc = tid & 1;           // 32B-half of 64B row

    auto load_stage = [&](int s, int k0) {
        uint32_t st = sb + (uint32_t)s * STG_SZ + (uint32_t)lr * RS + (uint32_t)lc * 32;
        size_t go = (size_t)lr * K + k0 + lc * 16;
        cp16(st,            gA + go); cp16(st + 16,         gA + go + 8);
        cp16(st + OFF_B,    gB + go); cp16(st + OFF_B + 16, gB + go + 8);
        CP_COMMIT();
    };

    load_stage(0, 0);
    load_stage(1, 32);
    load_stage(2, 64);

    const int wid = tid >> 5, L = tid & 31;
    const int mbase = (wid >> 2) * 64;   // warp row block (0,64)
    const int nbase = (wid & 3) * 32;    // warp col block (0,32,64,96)

    float acc[4][4][4];
    #pragma unroll
    for (int i = 0; i < 4; i++)
        #pragma unroll
        for (int j = 0; j < 4; j++)
            #pragma unroll
            for (int q = 0; q < 4; q++) acc[i][j][q] = 0.0f;

    const uint32_t aoff = (uint32_t)(mbase + (L & 15)) * RS + (uint32_t)(((L >> 4) & 1) * 16);
    const uint32_t boff = (uint32_t)(nbase + (L & 7) + ((L >> 4) & 1) * 8) * RS
                        + (uint32_t)(((L >> 3) & 1) * 16);

    for (int kt = 0; kt < KIT; kt++) {
        CP_WAIT2();
        __syncthreads();
        if (kt + 3 < KIT) load_stage((kt + 3) & 3, (kt + 3) * 32);
        else              CP_COMMIT();   // keep group window sliding for WAIT2

        const uint32_t sbase = sb + (uint32_t)(kt & 3) * STG_SZ;

        // ---- issue ALL fragment loads for both k-halves up front (independent) ----
        uint32_t ah0[4][4], bh0[2][4], ah1[4][4], bh1[2][4];
        const uint32_t ka = sbase + aoff;
        const uint32_t kb = sbase + OFF_B + boff;
        #pragma unroll
        for (int mt = 0; mt < 4; mt++) ldsm4(ah0[mt], ka + mt * (16 * RS));
        #pragma unroll
        for (int nt2 = 0; nt2 < 2; nt2++) ldsm4(bh0[nt2], kb + nt2 * (16 * RS));
        #pragma unroll
        for (int mt = 0; mt < 4; mt++) ldsm4(ah1[mt], ka + 32 + mt * (16 * RS));
        #pragma unroll
        for (int nt2 = 0; nt2 < 2; nt2++) ldsm4(bh1[nt2], kb + 32 + nt2 * (16 * RS));

        // ---- MMAs ----
        #pragma unroll
        for (int mt = 0; mt < 4; mt++)
            #pragma unroll
            for (int nt = 0; nt < 4; nt++)
                mma_f16(acc[mt][nt], ah0[mt],
                        bh0[nt >> 1][(nt & 1) * 2], bh0[nt >> 1][(nt & 1) * 2 + 1]);
        #pragma unroll
        for (int mt = 0; mt < 4; mt++)
            #pragma unroll
            for (int nt = 0; nt < 4; nt++)
                mma_f16(acc[mt][nt], ah1[mt],
                        bh1[nt >> 1][(nt & 1) * 2], bh1[nt >> 1][(nt & 1) * 2 + 1]);
    }

    // ---------------- epilogue: bias + relu ----------------
    const int g  = L >> 2;
    const int t2 = (L & 3) * 2;
    #pragma unroll
    for (int mt = 0; mt < 4; mt++) {
        const int r0 = bm + mbase + mt * 16 + g;
        #pragma unroll
        for (int nt = 0; nt < 4; nt++) {
            const int col = nbase + nt * 8 + t2;
            const float b0v = bias_sm[col], b1v = bias_sm[col + 1];
            float v00 = fmaxf(acc[mt][nt][0] + b0v, 0.0f);
            float v01 = fmaxf(acc[mt][nt][1] + b1v, 0.0f);
            float v10 = fmaxf(acc[mt][nt][2] + b0v, 0.0f);
            float v11 = fmaxf(acc[mt][nt][3] + b1v, 0.0f);
            const size_t o0 = ((size_t)e * BATCH + r0) * OUTN + bn + col;
            const size_t o1 = o0 + (size_t)8 * OUTN;
            if (SPLIT_OUT) {
                *reinterpret_cast<uint32_t*>(&g_h[o0]) = pk2h(v00, v01);
                *reinterpret_cast<uint32_t*>(&g_h[o1]) = pk2h(v10, v11);
            } else {
                *reinterpret_cast<uint32_t*>(&g_eo[o0]) = pk2h(v00, v01);
                *reinterpret_cast<uint32_t*>(&g_eo[o1]) = pk2h(v10, v11);
            }
        }
    }
}

// ---------------- weight transpose + convert: [e][K][N] -> [e][N][K] fp16 ----
__global__ __launch_bounds__(256) void wtrans_kernel(
    const float* __restrict__ Wsp, const float* __restrict__ Wsh,
    __half* __restrict__ dst, int K, int N)
{
    __shared__ float t[32][33];
    const int e = blockIdx.z;
    const float* src = (e < 12) ? Wsp + (size_t)e * K * N
                                : Wsh + (size_t)(e - 12) * K * N;
    const int n0 = blockIdx.x * 32, k0 = blockIdx.y * 32;
    const int c = threadIdx.x & 31, r8 = threadIdx.x >> 5;
    #pragma unroll
    for (int rr = 0; rr < 32; rr += 8)
        t[r8 + rr][c] = src[(size_t)(k0 + r8 + rr) * N + n0 + c];
    __syncthreads();
    #pragma unroll
    for (int rr = 0; rr < 32; rr += 8) {
        float v = t[c][r8 + rr];
        size_t o = ((size_t)e * N + n0 + r8 + rr) * K + k0 + c;
        dst[o] = __float2half_rn(v);
    }
}

// ---------------- gates + x fp16 conversion fused ----------------
// Task warps: 4 rows each; shared warps: 2 rows each. Gate math in fp32.
// Side effect: writes the fp16 copy of every x element into g_xh
// (task planes 0..2 and shared plane 3), replacing convert_x_kernel.
#define TASK_WARPS (TTASK * BATCH / 4)   // 6144
#define SH_WARPS   (BATCH / 2)           // 4096
__global__ __launch_bounds__(256) void gates_kernel(
    const float* __restrict__ x_tasks, const float* __restrict__ x_shared,
    const float* __restrict__ W_gate,  const float* __restrict__ b_gate,
    const float* __restrict__ W_gsh,   const float* __restrict__ b_gsh)
{
    const int warp = (blockIdx.x * blockDim.x + threadIdx.x) >> 5;
    const int lane = threadIdx.x & 31;

    if (warp < TASK_WARPS) {
        const int r0 = warp * 4;
        const int t  = r0 >> 13;
        const int b0 = r0 & (BATCH - 1);
        const float* x = x_tasks + ((size_t)t * BATCH + b0) * DIM;
        __half* xh = g_xh + ((size_t)t * BATCH + b0) * DIM;
        const float* W = W_gate + (size_t)t * DIM * 8;
        float s[4][8];
        #pragma unroll
        for (int r = 0; r < 4; r++)
            #pragma unroll
            for (int o = 0; o < 8; o++) s[r][o] = 0.0f;
        for (int d = lane; d < DIM; d += 32) {
            float4 w0 = *(const float4*)(W + (size_t)d * 8);
            float4 w1 = *(const float4*)(W + (size_t)d * 8 + 4);
            #pragma unroll
            for (int r = 0; r < 4; r++) {
                float xv = x[(size_t)r * DIM + d];
                xh[(size_t)r * DIM + d] = __float2half_rn(xv);
                s[r][0] += xv * w0.x; s[r][1] += xv * w0.y;
                s[r][2] += xv * w0.z; s[r][3] += xv * w0.w;
                s[r][4] += xv * w1.x; s[r][5] += xv * w1.y;
                s[r][6] += xv * w1.z; s[r][7] += xv * w1.w;
            }
        }
        #pragma unroll
        for (int r = 0; r < 4; r++)
            #pragma unroll
            for (int o = 0; o < 8; o++)
                #pragma unroll
                for (int off = 16; off > 0; off >>= 1)
                    s[r][o] += __shfl_xor_sync(0xffffffffu, s[r][o], off);
        if (lane == 0) {
            #pragma unroll
            for (int r = 0; r < 4; r++) {
                float mx = -1e30f;
                #pragma unroll
                for (int o = 0; o < 8; o++) { s[r][o] += b_gate[t * 8 + o]; mx = fmaxf(mx, s[r][o]); }
                float sum = 0.0f;
                #pragma unroll
                for (int o = 0; o < 8; o++) { s[r][o] = expf(s[r][o] - mx); sum += s[r][o]; }
                float inv = 1.0f / sum;
                #pragma unroll
                for (int o = 0; o < 8; o++)
                    g_gate[((size_t)t * BATCH + b0 + r) * 8 + o] = s[r][o] * inv;
            }
        }
    } else {
        const int b0 = (warp - TASK_WARPS) * 2;
        const float* x = x_shared + (size_t)b0 * DIM;
        __half* xh = g_xh + ((size_t)3 * BATCH + b0) * DIM;
        float s[2][16];
        #pragma unroll
        for (int r = 0; r < 2; r++)
            #pragma unroll
            for (int o = 0; o < 16; o++) s[r][o] = 0.0f;
        for (int d = lane; d < DIM; d += 32) {
            float4 w0 = *(const float4*)(W_gsh + (size_t)d * 16);
            float4 w1 = *(const float4*)(W_gsh + (size_t)d * 16 + 4);
            float4 w2 = *(const float4*)(W_gsh + (size_t)d * 16 + 8);
            float4 w3 = *(const float4*)(W_gsh + (size_t)d * 16 + 12);
            #pragma unroll
            for (int r = 0; r < 2; r++) {
                float xv = x[(size_t)r * DIM + d];
                xh[(size_t)r * DIM + d] = __float2half_rn(xv);
                s[r][ 0] += xv * w0.x; s[r][ 1] += xv * w0.y; s[r][ 2] += xv * w0.z; s[r][ 3] += xv * w0.w;
                s[r][ 4] += xv * w1.x; s[r][ 5] += xv * w1.y; s[r][ 6] += xv * w1.z; s[r][ 7] += xv * w1.w;
                s[r][ 8] += xv * w2.x; s[r][ 9] += xv * w2.y; s[r][10] += xv * w2.z; s[r][11] += xv * w2.w;
                s[r][12] += xv * w3.x; s[r][13] += xv * w3.y; s[r][14] += xv * w3.z; s[r][15] += xv * w3.w;
            }
        }
        #pragma unroll
        for (int r = 0; r < 2; r++)
            #pragma unroll
            for (int o = 0; o < 16; o++)
                #pragma unroll
                for (int off = 16; off > 0; off >>= 1)
                    s[r][o] += __shfl_xor_sync(0xffffffffu, s[r][o], off);
        if (lane == 0) {
            #pragma unroll
            for (int r = 0; r < 2; r++) {
                float mx = -1e30f;
                #pragma unroll
                for (int o = 0; o < 16; o++) { s[r][o] += b_gsh[o]; mx = fmaxf(mx, s[r][o]); }
                float sum = 0.0f;
                #pragma unroll
                for (int o = 0; o < 16; o++) { s[r][o] = expf(s[r][o] - mx); sum += s[r][o]; }
                float inv = 1.0f / sum;
                #pragma unroll
                for (int o = 0; o < 16; o++)
                    g_gsh[(size_t)(b0 + r) * 16 + o] = s[r][o] * inv;
            }
        }
    }
}

// ---------------- combine (eo in fp16) ----------------
__global__ __launch_bounds__(256) void combine_kernel(float* __restrict__ out)
{
    const int b = blockIdx.x;
    const int e = threadIdx.x;
    __shared__ float g[24];
    __shared__ float gs[16];

    if (threadIdx.x < 24)
        g[threadIdx.x] = g_gate[(size_t)(threadIdx.x >> 3) * BATCH * 8
                                + (size_t)b * 8 + (threadIdx.x & 7)];
    if (threadIdx.x >= 32 && threadIdx.x < 48)
        gs[threadIdx.x - 32] = g_gsh[(size_t)b * 16 + (threadIdx.x - 32)];
    __syncthreads();

    float a0 = 0.0f, a1 = 0.0f, a2 = 0.0f, a3 = 0.0f;
    const __half* eo = g_eo + (size_t)b * EDIM + e;

    #pragma unroll
    for (int j = 0; j < 12; j++) {
        float v = __half2float(eo[(size_t)j * BATCH * EDIM]);
        const int t = j >> 2;
        float gw = g[t * 8 + (j & 3)];
        if (t == 0)      a0 += gw * v;
        else if (t == 1) a1 += gw * v;
        else             a2 += gw * v;
        a3 += gs[j] * v;
    }
    #pragma unroll
    for (int s = 0; s < 4; s++) {
        float v = __half2float(eo[(size_t)(12 + s) * BATCH * EDIM]);
        a0 += g[0 * 8 + 4 + s] * v;
        a1 += g[1 * 8 + 4 + s] * v;
        a2 += g[2 * 8 + 4 + s] * v;
        a3 += gs[12 + s] * v;
    }

    const size_t o = (size_t)b * EDIM + e;
    const size_t plane = (size_t)BATCH * EDIM;
    out[o]             = a0;
    out[plane + o]     = a1;
    out[2 * plane + o] = a2;
    out[3 * plane + o] = a3;
}

// ---------------- host ----------------
extern "C" void kernel_launch(void* const* d_in, const int* in_sizes, int n_in,
                              void* d_out, int out_size)
{
    const float* x_tasks  = (const float*)d_in[0];
    const float* x_shared = (const float*)d_in[1];
    const float* W_spec1  = (const float*)d_in[2];
    const float* b_spec1  = (const float*)d_in[3];
    const float* W_spec2  = (const float*)d_in[4];
    const float* b_spec2  = (const float*)d_in[5];
    const float* W_sh1    = (const float*)d_in[6];
    const float* b_sh1    = (const float*)d_in[7];
    const float* W_sh2    = (const float*)d_in[8];
    const float* b_sh2    = (const float*)d_in[9];
    const float* W_gate   = (const float*)d_in[10];
    const float* b_gate   = (const float*)d_in[11];
    const float* W_gsh    = (const float*)d_in[12];
    const float* b_gsh    = (const float*)d_in[13];
    float* out = (float*)d_out;

    void *p_xh, *p_w1, *p_w2, *p_h;
    cudaGetSymbolAddress(&p_xh, g_xh);
    cudaGetSymbolAddress(&p_w1, g_w1);
    cudaGetSymbolAddress(&p_w2, g_w2);
    cudaGetSymbolAddress(&p_h, g_h);

    cudaFuncSetAttribute(gemm_kernel<1024, HID, true>,
                         cudaFuncAttributeMaxDynamicSharedMemorySize, SMEM_TT);
    cudaFuncSetAttribute(gemm_kernel<512, EDIM, false>,
                         cudaFuncAttributeMaxDynamicSharedMemorySize, SMEM_TT);

    // gates also produces g_xh (fp16 x) — must precede gemm1
    gates_kernel<<<(TASK_WARPS + SH_WARPS) / 8, 256>>>(
        x_tasks, x_shared, W_gate, b_gate, W_gsh, b_gsh);
    wtrans_kernel<<<dim3(HID / 32, DIM / 32, NEXP), 256>>>(
        W_spec1, W_sh1, (__half*)p_w1, DIM, HID);
    wtrans_kernel<<<dim3(EDIM / 32, HID / 32, NEXP), 256>>>(
        W_spec2, W_sh2, (__half*)p_w2, HID, EDIM);

    gemm_kernel<1024, HID, true><<<dim3(HID / 128, BATCH / 128, NEXP), 256, SMEM_TT>>>(
        (const __half*)p_xh, (const __half*)p_w1, b_spec1, b_sh1);
    gemm_kernel<512, EDIM, false><<<dim3(EDIM / 128, BATCH / 128, NEXP), 256, SMEM_TT>>>(
        (const __half*)p_h, (const __half*)p_w2, b_spec2, b_sh2);

    combine_kernel<<<BATCH, 256>>>(out);
}